// round 1
// baseline (speedup 1.0000x reference)
#include <cuda_runtime.h>
#include <cuda_bf16.h>

// Problem constants
#define HH   64
#define WW   128
#define CC   256
#define NPIX (HH * WW)          // 8192
#define NH   8
#define HD   32
#define C3   (3 * CC)           // 768
#define KK   7

// Scratch (device globals; no allocation allowed)
__device__ float g_qkv[NPIX * C3];   // 25 MB
__device__ float g_att[NPIX * CC];   // 8 MB

// ---------------------------------------------------------------------------
// Tiled fp32 GEMM with fused bias: C = A(MxK) * B(KxN) + bias(N)
// BM=BN=128, BK=16, 256 threads, 8x8 per-thread tile.
// Assumes M%128==0, N%128==0, K%16==0 (true for all three calls).
// ---------------------------------------------------------------------------
template <int BM, int BN, int BK, int TM, int TN>
__global__ __launch_bounds__(256, 2)
void sgemm_bias(const float* __restrict__ A, const float* __restrict__ B,
                const float* __restrict__ bias, float* __restrict__ C,
                int M, int N, int K)
{
    __shared__ float As[BM][BK + 1];   // +1 pad: conflict-free column reads
    __shared__ float Bs[BK][BN];

    const int tid = threadIdx.x;
    const int bx  = blockIdx.x;        // N tile
    const int by  = blockIdx.y;        // M tile

    const int tx = tid % (BN / TN);    // 0..15
    const int ty = tid / (BN / TN);    // 0..15

    // global->smem index precompute
    const int aRow  = tid / (BK / 4);  // 0..63
    const int aCol4 = tid % (BK / 4);  // 0..3
    const int bRow  = tid / (BN / 4);  // 0..7
    const int bCol4 = tid % (BN / 4);  // 0..31

    float acc[TM][TN];
#pragma unroll
    for (int i = 0; i < TM; i++)
#pragma unroll
        for (int j = 0; j < TN; j++) acc[i][j] = 0.0f;

    for (int k0 = 0; k0 < K; k0 += BK) {
        // Load A tile (BM x BK), 2 float4 per thread
#pragma unroll
        for (int it = 0; it < 2; it++) {
            int r = aRow + it * 64;
            float4 v = *(const float4*)&A[(size_t)(by * BM + r) * K + k0 + aCol4 * 4];
            As[r][aCol4 * 4 + 0] = v.x;
            As[r][aCol4 * 4 + 1] = v.y;
            As[r][aCol4 * 4 + 2] = v.z;
            As[r][aCol4 * 4 + 3] = v.w;
        }
        // Load B tile (BK x BN), 2 float4 per thread, coalesced
#pragma unroll
        for (int it = 0; it < 2; it++) {
            int r = bRow + it * 8;
            *(float4*)&Bs[r][bCol4 * 4] =
                *(const float4*)&B[(size_t)(k0 + r) * N + bx * BN + bCol4 * 4];
        }
        __syncthreads();

#pragma unroll
        for (int k = 0; k < BK; k++) {
            float rm[TM], rn[TN];
#pragma unroll
            for (int i = 0; i < TM; i++) rm[i] = As[ty * TM + i][k];
#pragma unroll
            for (int j = 0; j < TN; j += 4) {
                float4 v = *(const float4*)&Bs[k][tx * TN + j];
                rn[j] = v.x; rn[j + 1] = v.y; rn[j + 2] = v.z; rn[j + 3] = v.w;
            }
#pragma unroll
            for (int i = 0; i < TM; i++)
#pragma unroll
                for (int j = 0; j < TN; j++)
                    acc[i][j] = fmaf(rm[i], rn[j], acc[i][j]);
        }
        __syncthreads();
    }

    // Epilogue: bias add + float4 stores
#pragma unroll
    for (int i = 0; i < TM; i++) {
        int row = by * BM + ty * TM + i;
#pragma unroll
        for (int j = 0; j < TN; j += 4) {
            int col = bx * BN + tx * TN + j;
            float4 o;
            o.x = acc[i][j + 0] + bias[col + 0];
            o.y = acc[i][j + 1] + bias[col + 1];
            o.z = acc[i][j + 2] + bias[col + 2];
            o.w = acc[i][j + 3] + bias[col + 3];
            *(float4*)&C[(size_t)row * N + col] = o;
        }
    }
}

// ---------------------------------------------------------------------------
// 2D neighborhood attention (7x7), one block = 8x8 pixel tile x 1 head.
// K/V window (up to 14x14 pixels x 32 dims) staged in dynamic smem.
// One warp per tile row; lane = head-dim; butterfly-reduced dot products.
// ---------------------------------------------------------------------------
__global__ __launch_bounds__(256, 1)
void na_attn(const float* __restrict__ qkv, float* __restrict__ out)
{
    extern __shared__ float sm[];

    const int c0   = blockIdx.x * 8;
    const int r0   = blockIdx.y * 8;
    const int head = blockIdx.z;

    const int rlo = max(r0 - 3, 0);
    const int rhi = min(r0 + 10, HH - 1);
    const int nr  = rhi - rlo + 1;
    const int clo = max(c0 - 3, 0);
    const int chi = min(c0 + 10, WW - 1);
    const int nc  = chi - clo + 1;
    const int npx = nr * nc;

    float* sK = sm;
    float* sV = sm + npx * HD;

    const int tid = threadIdx.x;

    // Cooperative load of K and V window for this head (float4 per chunk)
    for (int t = tid; t < npx * (HD / 4); t += 256) {
        int p = t >> 3;            // pixel within window
        int f = t & 7;             // float4 index within 32 dims
        int gy = rlo + p / nc;
        int gx = clo + p % nc;
        const float* base = qkv + (size_t)(gy * WW + gx) * C3 + head * HD;
        *(float4*)&sK[p * HD + f * 4] = *(const float4*)(base + CC + f * 4);
        *(float4*)&sV[p * HD + f * 4] = *(const float4*)(base + 2 * CC + f * 4);
    }
    __syncthreads();

    const int warp = tid >> 5;
    const int lane = tid & 31;
    const int gy   = r0 + warp;
    const float scale = 0.17677669529663687f;   // 1/sqrt(32)

    const int sy = min(max(gy - 3, 0), HH - KK) - rlo;

    for (int lx = 0; lx < 8; lx++) {
        const int gx = c0 + lx;
        float qv = qkv[(size_t)(gy * WW + gx) * C3 + head * HD + lane] * scale;
        const int sx = min(max(gx - 3, 0), WW - KK) - clo;

        // Pass 1: 49 dot products via butterfly reductions (ILP across nbrs)
        float sc[KK * KK];
#pragma unroll
        for (int p = 0; p < KK; p++) {
#pragma unroll
            for (int q = 0; q < KK; q++) {
                float s = qv * sK[((sy + p) * nc + (sx + q)) * HD + lane];
                s += __shfl_xor_sync(0xffffffffu, s, 16);
                s += __shfl_xor_sync(0xffffffffu, s, 8);
                s += __shfl_xor_sync(0xffffffffu, s, 4);
                s += __shfl_xor_sync(0xffffffffu, s, 2);
                s += __shfl_xor_sync(0xffffffffu, s, 1);
                sc[p * KK + q] = s;
            }
        }

        float m = sc[0];
#pragma unroll
        for (int i = 1; i < KK * KK; i++) m = fmaxf(m, sc[i]);

        // Pass 2: exp + weighted V accumulation (lane owns one head-dim)
        float l = 0.0f, acc = 0.0f;
#pragma unroll
        for (int p = 0; p < KK; p++) {
#pragma unroll
            for (int q = 0; q < KK; q++) {
                float e = __expf(sc[p * KK + q] - m);
                l += e;
                acc = fmaf(e, sV[((sy + p) * nc + (sx + q)) * HD + lane], acc);
            }
        }

        out[(size_t)(gy * WW + gx) * CC + head * HD + lane] = acc / l;
    }
}

// ---------------------------------------------------------------------------
// kernel_launch
// ---------------------------------------------------------------------------
extern "C" void kernel_launch(void* const* d_in, const int* in_sizes, int n_in,
                              void* d_out, int out_size)
{
    const float* x      = (const float*)d_in[0];
    const float* w_qkv  = (const float*)d_in[1];
    const float* b_qkv  = (const float*)d_in[2];
    const float* w_proj = (const float*)d_in[3];
    const float* b_proj = (const float*)d_in[4];
    float* out = (float*)d_out;

    float* qkv;
    float* att;
    cudaGetSymbolAddress((void**)&qkv, g_qkv);
    cudaGetSymbolAddress((void**)&att, g_att);

    // 1) QKV projection: [8192,256] @ [256,768] + b
    {
        dim3 grid(C3 / 128, NPIX / 128);
        sgemm_bias<128, 128, 16, 8, 8><<<grid, 256>>>(x, w_qkv, b_qkv, qkv,
                                                      NPIX, C3, CC);
    }

    // 2) Neighborhood attention
    {
        const int smem = 2 * 14 * 14 * HD * (int)sizeof(float);  // 50176 B
        cudaFuncSetAttribute(na_attn, cudaFuncAttributeMaxDynamicSharedMemorySize,
                             smem);
        dim3 grid(WW / 8, HH / 8, NH);
        na_attn<<<grid, 256, smem>>>(qkv, att);
    }

    // 3) Output projection: [8192,256] @ [256,256] + b
    {
        dim3 grid(CC / 128, NPIX / 128);
        sgemm_bias<128, 128, 16, 8, 8><<<grid, 256>>>(att, w_proj, b_proj, out,
                                                      NPIX, CC, CC);
    }
}